// round 14
// baseline (speedup 1.0000x reference)
#include <cuda_runtime.h>
#include <cuda_bf16.h>
#include <cstdint>

// PDF sampler: 2 rays/warp (16 lanes/ray, 4 elems/lane), owner-computes,
// bin-major owner loops, cheap ceil-based counts, pad==0 fast path,
// saturate-fused clamp. 32-reg full-occupancy build. (R11 base + 2 micro-cuts)

#define ND 64
#define NS 32
#define NOUT 96
#define EPS 1e-5f
#define WPB 8
#define FULL 0xffffffffu

static __device__ __forceinline__ int count_u_below(float c) {
    // ~#{ j in [0,32) : (2j+1)/64 < c } = min(ceil(32c - 0.5), 32).
    // c >= 0 always -> ceil(32c-0.5) >= 0: no low clamp needed.
    // Off-by-one possible only at ulp-level bin boundaries (value-continuous);
    // merge correctness preserved by probe/anytie + monotone ballot guard.
    return min(__float2int_ru(fmaf(32.0f, c, -0.5f)), 32);
}

__global__ __launch_bounds__(WPB * 32, 8)
void pdf_sampler_kernel(const float* __restrict__ weights,
                        const float* __restrict__ s_offsets,
                        float* __restrict__ out,
                        int num_rays) {
    __shared__ __align__(16) float s_new[WPB][2][NS];   // sorted new samples
    __shared__ __align__(16) float s_out[WPB][2 * NOUT];

    const int warp = threadIdx.x >> 5;
    const int lane = threadIdx.x & 31;
    const int half = lane >> 4;          // ray within warp
    const int hl   = lane & 15;          // lane within 16-lane segment
    const int k0   = 4 * hl;

    const int ray_base = (blockIdx.x * WPB + warp) * 2;
    if (ray_base >= num_rays) return;    // warp-uniform
    const int ray   = ray_base + half;
    const int ray_c = min(ray, num_rays - 1);

    const float4 wv = reinterpret_cast<const float4*>(weights   + (size_t)ray_c * ND)[hl];
    const float4 ov = reinterpret_cast<const float4*>(s_offsets + (size_t)ray_c * ND)[hl];

    // ---- in-lane partials + segmented inclusive scan (width 16) ----
    const float p1 = wv.x;
    const float p2 = p1 + wv.y;
    const float p3 = p2 + wv.z;
    const float p4 = p3 + wv.w;
    float scan = p4;
    #pragma unroll
    for (int d = 1; d < 16; d <<= 1) {
        float v = __shfl_up_sync(FULL, scan, d, 16);
        if (hl >= d) scan += v;
    }
    const float e0    = scan - p4;                      // exclusive prefix
    const float total = __shfl_sync(FULL, scan, 15, 16);
    const float pad   = fmaxf(EPS - total, 0.0f);
    const float inv   = __fdividef(1.0f, total + pad);

    const float cum1 = e0 + p1;
    const float cum2 = e0 + p2;
    const float cum3 = e0 + p3;

    float c1, c2, c3, c4;
    if (__ballot_sync(FULL, pad != 0.0f)) {             // ~never taken
        const float pad64 = pad * (1.0f / 64.0f);
        c1 = (cum1 + (float)(k0 + 1) * pad64) * inv;
        c2 = (cum2 + (float)(k0 + 2) * pad64) * inv;
        c3 = (cum3 + (float)(k0 + 3) * pad64) * inv;
        c4 = (scan + (float)(k0 + 4) * pad64) * inv;
    } else {                                            // pad == 0 fast path
        c1 = cum1 * inv;
        c2 = cum2 * inv;
        c3 = cum3 * inv;
        c4 = scan * inv;
    }

    float c0 = __shfl_up_sync(FULL, c4, 1, 16);         // cdf[k0]
    if (hl == 0) c0 = 0.0f;

    // ---- counts N_k ~ #{u < cdf[k]} ----
    // c1<=c2<=c3 provable in fp (monotone adds x same positive inv), so
    // n1<=n2<=n3 automatic; only c4 (from scan, not e0+p4) can invert vs c3.
    int n1 = count_u_below(c1);
    int n2 = count_u_below(c2);
    int n3 = count_u_below(c3);
    int n4 = max(n3, count_u_below(c4));
    if (hl == 15) n4 = 32;                                   // cdf[64]=1 exactly

    int ne = __shfl_up_sync(FULL, n4, 1, 16);                // N_{k0}
    if (hl == 0) ne = 0;

    // cross-lane monotone? (ulp guard; ~never fires)
    if (__ballot_sync(FULL, n1 < ne)) {
        int P = n4;
        #pragma unroll
        for (int d = 1; d < 16; d <<= 1) {
            int v = __shfl_up_sync(FULL, P, d, 16);
            if (hl >= d) P = max(P, v);
        }
        ne = __shfl_up_sync(FULL, P, 1, 16);
        if (hl == 0) ne = 0;
        n1 = max(n1, ne); n2 = max(n2, n1); n3 = max(n3, n2); n4 = P;
    }

    // bin-4 right-side values (next lane's ov.x / own c4); hl==15: clamp to 63
    float c4x = c4;
    float o4x = __shfl_down_sync(FULL, ov.x, 1, 16);
    if (hl == 15) { c4x = c3; o4x = ov.w; }

    float* o  = s_out[warp] + half * NOUT;
    float* sN = s_new[warp][half];
    const float* goff = s_offsets + (size_t)ray_c * ND;      // rare deep-probe only

    // ---- bin-major owner loops; per-bin invariants hoisted.
    //      invden=inf when den==0: t -> 1 (+inf) or 0 (NaN) via __saturatef,
    //      matching reference nan_to_num + clip exactly. ----
    bool anytie = false;
    #define BIN_LOOP(JLO, JHI, CL, CR, OL, ORR, IDX, CHK)                     \
    {                                                                         \
        const float invden = __fdividef(1.0f, (CR) - (CL));                   \
        const float dor    = (ORR) - (OL);                                    \
        float u = fmaf((float)(JLO), 0.03125f, 0.015625f);  /* exact */       \
        for (int j = (JLO); j < (JHI); ++j, u += 0.03125f) {                  \
            const float t  = __saturatef((u - (CL)) * invden);                \
            const float sn = fmaf(t, dor, (OL));                              \
            sN[j] = sn;                                                       \
            int r = (IDX);                                                    \
            if ((CHK) && sn >= (ORR)) {                                       \
                ++r;                                                          \
                while (r < ND && goff[r] <= sn) ++r;                          \
                anytie = true;                                                \
            }                                                                 \
            o[j + r] = sn;                                                    \
        }                                                                     \
    }
    BIN_LOOP(ne, n1, c0, c1,  ov.x, ov.y, k0 + 1, true)
    BIN_LOOP(n1, n2, c1, c2,  ov.y, ov.z, k0 + 2, true)
    BIN_LOOP(n2, n3, c2, c3,  ov.z, ov.w, k0 + 3, true)
    BIN_LOOP(n3, n4, c3, c4x, ov.w, o4x,  k0 + 4, (k0 + 4 < ND))
    #undef BIN_LOOP

    // ---- b-ranks: analytic unless a tie broke strictness (rare) ----
    int rb0 = ne, rb1 = n1, rb2 = n2, rb3 = n3;
    if (__ballot_sync(FULL, anytie)) {                   // warp-uniform branch
        __syncwarp();
        const float bv[4] = {ov.x, ov.y, ov.z, ov.w};
        int rb[4];
        #pragma unroll
        for (int m = 0; m < 4; ++m) {
            int l = 0, h = NS;
            #pragma unroll
            for (int it = 0; it < 6; ++it) {
                if (l < h) { int mid = (l + h) >> 1; if (sN[mid] < bv[m]) l = mid + 1; else h = mid; }
            }
            rb[m] = l;
        }
        rb0 = rb[0]; rb1 = rb[1]; rb2 = rb[2]; rb3 = rb[3];
    }

    o[k0 + 0 + rb0] = ov.x;     // pos_b = k + rank_b = k + N_k
    o[k0 + 1 + rb1] = ov.y;
    o[k0 + 2 + rb2] = ov.z;
    o[k0 + 3 + rb3] = ov.w;
    __syncwarp();

    // ---- dense float4 output (2 rays = 192 contiguous floats) ----
    const int valid4 = min(48, (num_rays - ray_base) * (NOUT / 4));
    const float4* so = reinterpret_cast<const float4*>(s_out[warp]);
    float4* og = reinterpret_cast<float4*>(out + (size_t)ray_base * NOUT);
    if (lane < valid4)      og[lane]      = so[lane];
    if (lane + 32 < valid4) og[lane + 32] = so[lane + 32];
}

extern "C" void kernel_launch(void* const* d_in, const int* in_sizes, int n_in,
                              void* d_out, int out_size) {
    const float* weights   = (const float*)d_in[0];
    const float* s_offsets = (const float*)d_in[1];
    float* out = (float*)d_out;

    const int num_rays = in_sizes[0] / ND;
    const int rays_per_block = WPB * 2;
    const int blocks = (num_rays + rays_per_block - 1) / rays_per_block;
    pdf_sampler_kernel<<<blocks, WPB * 32>>>(weights, s_offsets, out, num_rays);
}

// round 15
// speedup vs baseline: 1.5244x; 1.5244x over previous
#include <cuda_runtime.h>
#include <cuda_bf16.h>
#include <cstdint>

// PDF sampler: 2 rays/warp (16 lanes/ray, 4 elems/lane), owner-computes,
// bin-major owner loops, cheap ceil-based counts, pad==0 fast path,
// saturate-fused clamp. 32-reg full-occupancy build. (R11 verified-best)

#define ND 64
#define NS 32
#define NOUT 96
#define EPS 1e-5f
#define WPB 8
#define FULL 0xffffffffu

static __device__ __forceinline__ int count_u_below(float c) {
    // ~#{ j in [0,32) : (2j+1)/64 < c } = clamp(ceil(32c - 0.5), 0, 32).
    // May be off by 1 only when 32c-0.5 rounds across an integer (u_j == c
    // at ulp level) -- value-continuous boundary; merge stays correct via
    // the probe/anytie machinery and monotone enforcement below.
    return min(max(__float2int_ru(fmaf(32.0f, c, -0.5f)), 0), 32);
}

__global__ __launch_bounds__(WPB * 32, 8)
void pdf_sampler_kernel(const float* __restrict__ weights,
                        const float* __restrict__ s_offsets,
                        float* __restrict__ out,
                        int num_rays) {
    __shared__ __align__(16) float s_new[WPB][2][NS];   // sorted new samples
    __shared__ __align__(16) float s_out[WPB][2 * NOUT];

    const int warp = threadIdx.x >> 5;
    const int lane = threadIdx.x & 31;
    const int half = lane >> 4;          // ray within warp
    const int hl   = lane & 15;          // lane within 16-lane segment
    const int k0   = 4 * hl;

    const int ray_base = (blockIdx.x * WPB + warp) * 2;
    if (ray_base >= num_rays) return;    // warp-uniform
    const int ray   = ray_base + half;
    const int ray_c = min(ray, num_rays - 1);

    const float4 wv = reinterpret_cast<const float4*>(weights   + (size_t)ray_c * ND)[hl];
    const float4 ov = reinterpret_cast<const float4*>(s_offsets + (size_t)ray_c * ND)[hl];

    // ---- in-lane partials + segmented inclusive scan (width 16) ----
    const float p1 = wv.x;
    const float p2 = p1 + wv.y;
    const float p3 = p2 + wv.z;
    const float p4 = p3 + wv.w;
    float scan = p4;
    #pragma unroll
    for (int d = 1; d < 16; d <<= 1) {
        float v = __shfl_up_sync(FULL, scan, d, 16);
        if (hl >= d) scan += v;
    }
    const float e0    = scan - p4;                      // exclusive prefix
    const float total = __shfl_sync(FULL, scan, 15, 16);
    const float pad   = fmaxf(EPS - total, 0.0f);
    const float inv   = __fdividef(1.0f, total + pad);

    const float cum1 = e0 + p1;
    const float cum2 = e0 + p2;
    const float cum3 = e0 + p3;

    float c1, c2, c3, c4;
    if (__ballot_sync(FULL, pad != 0.0f)) {             // ~never taken
        const float pad64 = pad * (1.0f / 64.0f);
        c1 = (cum1 + (float)(k0 + 1) * pad64) * inv;
        c2 = (cum2 + (float)(k0 + 2) * pad64) * inv;
        c3 = (cum3 + (float)(k0 + 3) * pad64) * inv;
        c4 = (scan + (float)(k0 + 4) * pad64) * inv;
    } else {                                            // pad == 0 fast path
        c1 = cum1 * inv;
        c2 = cum2 * inv;
        c3 = cum3 * inv;
        c4 = scan * inv;
    }

    float c0 = __shfl_up_sync(FULL, c4, 1, 16);         // cdf[k0]
    if (hl == 0) c0 = 0.0f;

    // ---- counts N_k ~ #{u < cdf[k]} ----
    int n1 = count_u_below(c1);
    int n2 = count_u_below(c2);
    int n3 = count_u_below(c3);
    int n4 = count_u_below(c4);
    n2 = max(n1, n2); n3 = max(n2, n3); n4 = max(n3, n4);   // in-lane monotone
    if (hl == 15) n4 = 32;                                   // cdf[64]=1 exactly

    int ne = __shfl_up_sync(FULL, n4, 1, 16);                // N_{k0}
    if (hl == 0) ne = 0;

    // cross-lane monotone? (ulp guard; ~never fires)
    if (__ballot_sync(FULL, n1 < ne)) {
        int P = n4;
        #pragma unroll
        for (int d = 1; d < 16; d <<= 1) {
            int v = __shfl_up_sync(FULL, P, d, 16);
            if (hl >= d) P = max(P, v);
        }
        ne = __shfl_up_sync(FULL, P, 1, 16);
        if (hl == 0) ne = 0;
        n1 = max(n1, ne); n2 = max(n2, n1); n3 = max(n3, n2); n4 = P;
    }

    // bin-4 right-side values (next lane's ov.x / own c4); hl==15: clamp to 63
    float c4x = c4;
    float o4x = __shfl_down_sync(FULL, ov.x, 1, 16);
    if (hl == 15) { c4x = c3; o4x = ov.w; }

    float* o  = s_out[warp] + half * NOUT;
    float* sN = s_new[warp][half];
    const float* goff = s_offsets + (size_t)ray_c * ND;      // rare deep-probe only

    // ---- bin-major owner loops; per-bin invariants hoisted.
    //      invden=inf when den==0: t = num*inf -> +inf->1 / NaN->0 via
    //      __saturatef, matching reference nan_to_num + clip exactly. ----
    bool anytie = false;
    #define BIN_LOOP(JLO, JHI, CL, CR, OL, ORR, IDX, CHK)                     \
    {                                                                         \
        const float invden = __fdividef(1.0f, (CR) - (CL));                   \
        const float dor    = (ORR) - (OL);                                    \
        float u = fmaf((float)(JLO), 0.03125f, 0.015625f);  /* exact */       \
        for (int j = (JLO); j < (JHI); ++j, u += 0.03125f) {                  \
            const float t  = __saturatef((u - (CL)) * invden);                \
            const float sn = fmaf(t, dor, (OL));                              \
            sN[j] = sn;                                                       \
            int r = (IDX);                                                    \
            if ((CHK) && sn >= (ORR)) {                                       \
                ++r;                                                          \
                while (r < ND && goff[r] <= sn) ++r;                          \
                anytie = true;                                                \
            }                                                                 \
            o[j + r] = sn;                                                    \
        }                                                                     \
    }
    BIN_LOOP(ne, n1, c0, c1,  ov.x, ov.y, k0 + 1, true)          // k0+1 <= 61 < ND
    BIN_LOOP(n1, n2, c1, c2,  ov.y, ov.z, k0 + 2, true)
    BIN_LOOP(n2, n3, c2, c3,  ov.z, ov.w, k0 + 3, true)
    BIN_LOOP(n3, n4, c3, c4x, ov.w, o4x,  k0 + 4, (k0 + 4 < ND))
    #undef BIN_LOOP

    // ---- b-ranks: analytic unless a tie broke strictness (rare) ----
    int rb0 = ne, rb1 = n1, rb2 = n2, rb3 = n3;
    if (__ballot_sync(FULL, anytie)) {                   // warp-uniform branch
        __syncwarp();
        const float bv[4] = {ov.x, ov.y, ov.z, ov.w};
        int rb[4];
        #pragma unroll
        for (int m = 0; m < 4; ++m) {
            int l = 0, h = NS;
            #pragma unroll
            for (int it = 0; it < 6; ++it) {
                if (l < h) { int mid = (l + h) >> 1; if (sN[mid] < bv[m]) l = mid + 1; else h = mid; }
            }
            rb[m] = l;
        }
        rb0 = rb[0]; rb1 = rb[1]; rb2 = rb[2]; rb3 = rb[3];
    }

    o[k0 + 0 + rb0] = ov.x;     // pos_b = k + rank_b = k + N_k
    o[k0 + 1 + rb1] = ov.y;
    o[k0 + 2 + rb2] = ov.z;
    o[k0 + 3 + rb3] = ov.w;
    __syncwarp();

    // ---- dense float4 output (2 rays = 192 contiguous floats) ----
    const int valid4 = min(48, (num_rays - ray_base) * (NOUT / 4));
    const float4* so = reinterpret_cast<const float4*>(s_out[warp]);
    float4* og = reinterpret_cast<float4*>(out + (size_t)ray_base * NOUT);
    if (lane < valid4)      og[lane]      = so[lane];
    if (lane + 32 < valid4) og[lane + 32] = so[lane + 32];
}

extern "C" void kernel_launch(void* const* d_in, const int* in_sizes, int n_in,
                              void* d_out, int out_size) {
    const float* weights   = (const float*)d_in[0];
    const float* s_offsets = (const float*)d_in[1];
    float* out = (float*)d_out;

    const int num_rays = in_sizes[0] / ND;
    const int rays_per_block = WPB * 2;
    const int blocks = (num_rays + rays_per_block - 1) / rays_per_block;
    pdf_sampler_kernel<<<blocks, WPB * 32>>>(weights, s_offsets, out, num_rays);
}

// round 16
// speedup vs baseline: 1.5312x; 1.0045x over previous
#include <cuda_runtime.h>
#include <cuda_bf16.h>
#include <cstdint>

// PDF sampler: 2 rays/warp (16 lanes/ray, 4 elems/lane), owner-computes,
// bin-major owner loops, cheap ceil-based counts, pad==0 fast path,
// saturate-fused clamp. R11 body, 128-thread blocks (16 CTAs/SM).

#define ND 64
#define NS 32
#define NOUT 96
#define EPS 1e-5f
#define WPB 4
#define FULL 0xffffffffu

static __device__ __forceinline__ int count_u_below(float c) {
    // ~#{ j in [0,32) : (2j+1)/64 < c } = clamp(ceil(32c - 0.5), 0, 32).
    // May be off by 1 only when 32c-0.5 rounds across an integer (u_j == c
    // at ulp level) -- value-continuous boundary; merge stays correct via
    // the probe/anytie machinery and monotone enforcement below.
    return min(max(__float2int_ru(fmaf(32.0f, c, -0.5f)), 0), 32);
}

__global__ __launch_bounds__(WPB * 32, 16)
void pdf_sampler_kernel(const float* __restrict__ weights,
                        const float* __restrict__ s_offsets,
                        float* __restrict__ out,
                        int num_rays) {
    __shared__ __align__(16) float s_new[WPB][2][NS];   // sorted new samples
    __shared__ __align__(16) float s_out[WPB][2 * NOUT];

    const int warp = threadIdx.x >> 5;
    const int lane = threadIdx.x & 31;
    const int half = lane >> 4;          // ray within warp
    const int hl   = lane & 15;          // lane within 16-lane segment
    const int k0   = 4 * hl;

    const int ray_base = (blockIdx.x * WPB + warp) * 2;
    if (ray_base >= num_rays) return;    // warp-uniform
    const int ray   = ray_base + half;
    const int ray_c = min(ray, num_rays - 1);

    const float4 wv = reinterpret_cast<const float4*>(weights   + (size_t)ray_c * ND)[hl];
    const float4 ov = reinterpret_cast<const float4*>(s_offsets + (size_t)ray_c * ND)[hl];

    // ---- in-lane partials + segmented inclusive scan (width 16) ----
    const float p1 = wv.x;
    const float p2 = p1 + wv.y;
    const float p3 = p2 + wv.z;
    const float p4 = p3 + wv.w;
    float scan = p4;
    #pragma unroll
    for (int d = 1; d < 16; d <<= 1) {
        float v = __shfl_up_sync(FULL, scan, d, 16);
        if (hl >= d) scan += v;
    }
    const float e0    = scan - p4;                      // exclusive prefix
    const float total = __shfl_sync(FULL, scan, 15, 16);
    const float pad   = fmaxf(EPS - total, 0.0f);
    const float inv   = __fdividef(1.0f, total + pad);

    const float cum1 = e0 + p1;
    const float cum2 = e0 + p2;
    const float cum3 = e0 + p3;

    float c1, c2, c3, c4;
    if (__ballot_sync(FULL, pad != 0.0f)) {             // ~never taken
        const float pad64 = pad * (1.0f / 64.0f);
        c1 = (cum1 + (float)(k0 + 1) * pad64) * inv;
        c2 = (cum2 + (float)(k0 + 2) * pad64) * inv;
        c3 = (cum3 + (float)(k0 + 3) * pad64) * inv;
        c4 = (scan + (float)(k0 + 4) * pad64) * inv;
    } else {                                            // pad == 0 fast path
        c1 = cum1 * inv;
        c2 = cum2 * inv;
        c3 = cum3 * inv;
        c4 = scan * inv;
    }

    float c0 = __shfl_up_sync(FULL, c4, 1, 16);         // cdf[k0]
    if (hl == 0) c0 = 0.0f;

    // ---- counts N_k ~ #{u < cdf[k]} ----
    int n1 = count_u_below(c1);
    int n2 = count_u_below(c2);
    int n3 = count_u_below(c3);
    int n4 = count_u_below(c4);
    n2 = max(n1, n2); n3 = max(n2, n3); n4 = max(n3, n4);   // in-lane monotone
    if (hl == 15) n4 = 32;                                   // cdf[64]=1 exactly

    int ne = __shfl_up_sync(FULL, n4, 1, 16);                // N_{k0}
    if (hl == 0) ne = 0;

    // cross-lane monotone? (ulp guard; ~never fires)
    if (__ballot_sync(FULL, n1 < ne)) {
        int P = n4;
        #pragma unroll
        for (int d = 1; d < 16; d <<= 1) {
            int v = __shfl_up_sync(FULL, P, d, 16);
            if (hl >= d) P = max(P, v);
        }
        ne = __shfl_up_sync(FULL, P, 1, 16);
        if (hl == 0) ne = 0;
        n1 = max(n1, ne); n2 = max(n2, n1); n3 = max(n3, n2); n4 = P;
    }

    // bin-4 right-side values (next lane's ov.x / own c4); hl==15: clamp to 63
    float c4x = c4;
    float o4x = __shfl_down_sync(FULL, ov.x, 1, 16);
    if (hl == 15) { c4x = c3; o4x = ov.w; }

    float* o  = s_out[warp] + half * NOUT;
    float* sN = s_new[warp][half];
    const float* goff = s_offsets + (size_t)ray_c * ND;      // rare deep-probe only

    // ---- bin-major owner loops; per-bin invariants hoisted.
    //      invden=inf when den==0: t = num*inf -> +inf->1 / NaN->0 via
    //      __saturatef, matching reference nan_to_num + clip exactly. ----
    bool anytie = false;
    #define BIN_LOOP(JLO, JHI, CL, CR, OL, ORR, IDX, CHK)                     \
    {                                                                         \
        const float invden = __fdividef(1.0f, (CR) - (CL));                   \
        const float dor    = (ORR) - (OL);                                    \
        float u = fmaf((float)(JLO), 0.03125f, 0.015625f);  /* exact */       \
        for (int j = (JLO); j < (JHI); ++j, u += 0.03125f) {                  \
            const float t  = __saturatef((u - (CL)) * invden);                \
            const float sn = fmaf(t, dor, (OL));                              \
            sN[j] = sn;                                                       \
            int r = (IDX);                                                    \
            if ((CHK) && sn >= (ORR)) {                                       \
                ++r;                                                          \
                while (r < ND && goff[r] <= sn) ++r;                          \
                anytie = true;                                                \
            }                                                                 \
            o[j + r] = sn;                                                    \
        }                                                                     \
    }
    BIN_LOOP(ne, n1, c0, c1,  ov.x, ov.y, k0 + 1, true)          // k0+1 <= 61 < ND
    BIN_LOOP(n1, n2, c1, c2,  ov.y, ov.z, k0 + 2, true)
    BIN_LOOP(n2, n3, c2, c3,  ov.z, ov.w, k0 + 3, true)
    BIN_LOOP(n3, n4, c3, c4x, ov.w, o4x,  k0 + 4, (k0 + 4 < ND))
    #undef BIN_LOOP

    // ---- b-ranks: analytic unless a tie broke strictness (rare) ----
    int rb0 = ne, rb1 = n1, rb2 = n2, rb3 = n3;
    if (__ballot_sync(FULL, anytie)) {                   // warp-uniform branch
        __syncwarp();
        const float bv[4] = {ov.x, ov.y, ov.z, ov.w};
        int rb[4];
        #pragma unroll
        for (int m = 0; m < 4; ++m) {
            int l = 0, h = NS;
            #pragma unroll
            for (int it = 0; it < 6; ++it) {
                if (l < h) { int mid = (l + h) >> 1; if (sN[mid] < bv[m]) l = mid + 1; else h = mid; }
            }
            rb[m] = l;
        }
        rb0 = rb[0]; rb1 = rb[1]; rb2 = rb[2]; rb3 = rb[3];
    }

    o[k0 + 0 + rb0] = ov.x;     // pos_b = k + rank_b = k + N_k
    o[k0 + 1 + rb1] = ov.y;
    o[k0 + 2 + rb2] = ov.z;
    o[k0 + 3 + rb3] = ov.w;
    __syncwarp();

    // ---- dense float4 output (2 rays = 192 contiguous floats) ----
    const int valid4 = min(48, (num_rays - ray_base) * (NOUT / 4));
    const float4* so = reinterpret_cast<const float4*>(s_out[warp]);
    float4* og = reinterpret_cast<float4*>(out + (size_t)ray_base * NOUT);
    if (lane < valid4)      og[lane]      = so[lane];
    if (lane + 32 < valid4) og[lane + 32] = so[lane + 32];
}

extern "C" void kernel_launch(void* const* d_in, const int* in_sizes, int n_in,
                              void* d_out, int out_size) {
    const float* weights   = (const float*)d_in[0];
    const float* s_offsets = (const float*)d_in[1];
    float* out = (float*)d_out;

    const int num_rays = in_sizes[0] / ND;
    const int rays_per_block = WPB * 2;
    const int blocks = (num_rays + rays_per_block - 1) / rays_per_block;
    pdf_sampler_kernel<<<blocks, WPB * 32>>>(weights, s_offsets, out, num_rays);
}